// round 11
// baseline (speedup 1.0000x reference)
#include <cuda_runtime.h>
#include <cuda_fp16.h>
#include <stdint.h>

// Shapes (fixed)
#define B_  16
#define NS  64
#define SQ  2048
#define DM  1024
#define TK  768

// ---------------- scratch (device globals) ----------------------------------
__device__ __align__(16) __half g_tokens_h[(size_t)B_*SQ*TK];            // A of proj
__device__ __align__(16) __half g_Wp_h[TK*DM];                           // B of proj
__device__ __align__(16) __half g_Wg_h[3*(size_t)2*DM*DM];               // [Wu | Wr | Wn]
__device__ __align__(16) __half g_ps_h[B_*NS*DM];                        // A of scores
__device__ __align__(16) __half g_tok_h[(size_t)B_*SQ*DM];               // B of scores/routed
__device__ __align__(16) __half g_attn_h[B_*NS*SQ];                      // scores -> attn in place (fp16)
__device__ __align__(16) float g_routed[B_*NS*DM];
__device__ __align__(16) __half g_cat_h[B_*NS*2*DM];                     // A of gates
__device__ __align__(16) __half g_cat2_h[B_*NS*2*DM];                    // A of cand
__device__ __align__(16) float g_u[B_*NS*DM];
__device__ __align__(16) float g_new[B_*NS*DM];

// ---------------- helpers ----------------------------------------------------
__device__ __forceinline__ unsigned s32(const void* p) {
    return (unsigned)__cvta_generic_to_shared(p);
}
__device__ __forceinline__ void cp16(unsigned dst, const void* src) {
    asm volatile("cp.async.cg.shared.global [%0], [%1], 16;\n" :: "r"(dst), "l"(src) : "memory");
}
__device__ __forceinline__ void cp_commit() { asm volatile("cp.async.commit_group;\n" ::); }
__device__ __forceinline__ void ldm_x4(uint32_t* r, unsigned a) {
    asm volatile("ldmatrix.sync.aligned.m8n8.x4.shared.b16 {%0,%1,%2,%3}, [%4];\n"
                 : "=r"(r[0]), "=r"(r[1]), "=r"(r[2]), "=r"(r[3]) : "r"(a));
}
__device__ __forceinline__ void ldm_x4_t(uint32_t* r, unsigned a) {
    asm volatile("ldmatrix.sync.aligned.m8n8.x4.trans.shared.b16 {%0,%1,%2,%3}, [%4];\n"
                 : "=r"(r[0]), "=r"(r[1]), "=r"(r[2]), "=r"(r[3]) : "r"(a));
}
__device__ __forceinline__ void mma16816(float* c, const uint32_t* a, const uint32_t* b) {
    asm volatile("mma.sync.aligned.m16n8k16.row.col.f32.f16.f16.f32 "
                 "{%0,%1,%2,%3}, {%4,%5,%6,%7}, {%8,%9}, {%0,%1,%2,%3};\n"
                 : "+f"(c[0]), "+f"(c[1]), "+f"(c[2]), "+f"(c[3])
                 : "r"(a[0]), "r"(a[1]), "r"(a[2]), "r"(a[3]), "r"(b[0]), "r"(b[1]));
}
__device__ __forceinline__ float warpSum(float v) {
#pragma unroll
    for (int o = 16; o; o >>= 1) v += __shfl_xor_sync(0xffffffffu, v, o);
    return v;
}
__device__ __forceinline__ float warpMax(float v) {
#pragma unroll
    for (int o = 16; o; o >>= 1) v = fmaxf(v, __shfl_xor_sync(0xffffffffu, v, o));
    return v;
}

// ---------------- fused vectorized epilogues ----------------------------------
// EPI: 0=tok(+bias) fp16  1=scores scale->fp16  2=routed  34=u/r gates  5=cand
template<int EPI>
__device__ __forceinline__ void epi2(float a0, float a1, size_t gr, int c, int z,
                                     const float* __restrict__ bias,
                                     const float* __restrict__ aux) {
    if constexpr (EPI == 0) {
        size_t i = gr * DM + c;
        *reinterpret_cast<__half2*>(&g_tok_h[i]) =
            __half2(__float2half_rn(a0 + bias[c]), __float2half_rn(a1 + bias[c + 1]));
    } else if constexpr (EPI == 1) {
        *reinterpret_cast<__half2*>(&g_attn_h[gr * SQ + c]) =
            __half2(__float2half_rn(a0 * 0.03125f), __float2half_rn(a1 * 0.03125f));
    } else if constexpr (EPI == 2) {
        *reinterpret_cast<float2*>(&g_routed[gr * DM + c]) = make_float2(a0, a1);
    } else if constexpr (EPI == 34) {
        float s0 = 1.0f / (1.0f + expf(-(a0 + bias[c])));
        float s1 = 1.0f / (1.0f + expf(-(a1 + bias[c + 1])));
        if (z == 0) {
            *reinterpret_cast<float2*>(&g_u[gr * DM + c]) = make_float2(s0, s1);
        } else {
            size_t i = gr * (2 * DM) + c;
            __half2 ps = *reinterpret_cast<__half2*>(&g_cat_h[i]);
            *reinterpret_cast<__half2*>(&g_cat2_h[i]) =
                __half2(__float2half_rn(s0 * __half2float(ps.x)),
                        __float2half_rn(s1 * __half2float(ps.y)));
        }
    } else {
        size_t i = gr * DM + c;
        float2 u = *reinterpret_cast<const float2*>(&g_u[i]);
        float2 pv = *reinterpret_cast<const float2*>(&aux[i]);
        float t0 = tanhf(a0 + bias[c]), t1 = tanhf(a1 + bias[c + 1]);
        *reinterpret_cast<float2*>(&g_new[i]) =
            make_float2((1.0f - u.x) * pv.x + u.x * t0,
                        (1.0f - u.y) * pv.y + u.y * t1);
    }
}

// ---------------- single-pass fp16 GEMM, 4-stage pipeline, unroll-4 -----------
template<int BM, int BN, int WM, int WN, bool BT, int EPI, int K, int LDA, int LDB>
__global__ __launch_bounds__(256, 2)
void gemm1(const __half* __restrict__ A, const __half* __restrict__ B,
           long long zA, long long zB, int rowz,
           const float* __restrict__ bias0, const float* __restrict__ bias1,
           const float* __restrict__ aux)
{
    constexpr int BK  = 32;
    constexpr int NST = 4;
    constexpr int WMs = BM / WM;
    constexpr int MT  = WM / 16, NT = WN / 8;
    constexpr int AST = BK + 8;
    constexpr int BST = BK + 8;
    constexpr int BNP = BN + 8;
    constexpr int nk  = K / BK;
    static_assert(nk % 4 == 0 && nk >= 4, "nk must be multiple of 4");

    extern __shared__ __align__(16) __half sm[];
    __half* As = sm;
    __half* Bs = sm + NST * BM * AST;

    const int tid = threadIdx.x, lane = tid & 31, wid = tid >> 5;
    const int wm = wid % WMs, wn = wid / WMs;
    const int brow = blockIdx.y * BM, bcol = blockIdx.x * BN;
    const int z = blockIdx.z;

    const __half* Ap = A + (size_t)z * zA + (size_t)brow * LDA;
    const __half* Bp = B + (size_t)z * zB;

    float acc[MT][NT][4];
#pragma unroll
    for (int i = 0; i < MT; ++i)
#pragma unroll
        for (int j = 0; j < NT; ++j)
#pragma unroll
            for (int e = 0; e < 4; ++e) acc[i][j][e] = 0.f;

    auto aOfs = [](int buf, int r, int c) -> int { return (buf * BM + r) * AST + c; };
    auto bOfs = [](int buf, int r, int c) -> int {
        return BT ? ((buf * BN + r) * BST + c) : ((buf * BK + r) * BNP + c);
    };

    constexpr int A_IT = BM * 4 / 256;
    constexpr int B_IT = BT ? (BN * 4 / 256) : (BK * BN / 8 / 256);

    auto loadSlab = [&](int buf, int k0) {
#pragma unroll
        for (int it = 0; it < A_IT; ++it) {
            int i = tid + it * 256;
            int r = i >> 2, c = (i & 3) * 8;
            cp16(s32(&As[aOfs(buf, r, c)]), Ap + (size_t)r * LDA + k0 + c);
        }
        if (BT) {
#pragma unroll
            for (int it = 0; it < B_IT; ++it) {
                int i = tid + it * 256;
                int n = i >> 2, c = (i & 3) * 8;
                cp16(s32(&Bs[bOfs(buf, n, c)]), Bp + (size_t)(bcol + n) * LDB + k0 + c);
            }
        } else {
#pragma unroll
            for (int it = 0; it < B_IT; ++it) {
                int i = tid + it * 256;
                int k = i / (BN / 8); int n8 = (i % (BN / 8)) * 8;
                cp16(s32(&Bs[bOfs(buf, k, n8)]), Bp + (size_t)(k0 + k) * LDB + bcol + n8);
            }
        }
        cp_commit();
    };

    loadSlab(0, 0);
    loadSlab(1, BK);
    loadSlab(2, 2 * BK);

#pragma unroll 4
    for (int ks = 0; ks < nk; ++ks) {
        const int buf = ks & 3;
        asm volatile("cp.async.wait_group 2;\n" ::);
        __syncthreads();
        if (ks + 3 < nk) loadSlab((ks + 3) & 3, (ks + 3) * BK);
        else cp_commit();

#pragma unroll
        for (int kk2 = 0; kk2 < 2; ++kk2) {
            uint32_t af[MT][4];
#pragma unroll
            for (int mt = 0; mt < MT; ++mt) {
                int row = wm * WM + mt * 16 + (lane & 15);
                int col = kk2 * 16 + (lane >> 4) * 8;
                ldm_x4(af[mt], s32(&As[aOfs(buf, row, col)]));
            }
            uint32_t bf[NT][2];
#pragma unroll
            for (int p = 0; p < NT / 2; ++p) {
                int nbase = wn * WN + p * 16;
                uint32_t t[4];
                if (BT) {
                    int r = nbase + (lane & 7) + ((lane >> 4) << 3);
                    int c = kk2 * 16 + ((lane >> 3) & 1) * 8;
                    ldm_x4(t, s32(&Bs[bOfs(buf, r, c)]));
                } else {
                    int k = kk2 * 16 + (lane & 15);
                    int nc = nbase + ((lane >> 4) << 3);
                    ldm_x4_t(t, s32(&Bs[bOfs(buf, k, nc)]));
                }
                bf[2*p][0]=t[0]; bf[2*p][1]=t[1]; bf[2*p+1][0]=t[2]; bf[2*p+1][1]=t[3];
            }
#pragma unroll
            for (int mt = 0; mt < MT; ++mt)
#pragma unroll
                for (int nt = 0; nt < NT; ++nt)
                    mma16816(acc[mt][nt], af[mt], bf[nt]);
        }
    }

    const float* bias = (z != 0 && bias1) ? bias1 : bias0;
#pragma unroll
    for (int mt = 0; mt < MT; ++mt) {
        int r0 = brow + wm * WM + mt * 16 + (lane >> 2);
#pragma unroll
        for (int nt = 0; nt < NT; ++nt) {
            int c0 = bcol + wn * WN + nt * 8 + ((lane & 3) << 1);
            size_t g0 = (size_t)z * rowz + r0;
            epi2<EPI>(acc[mt][nt][0], acc[mt][nt][1], g0,     c0, z, bias, aux);
            epi2<EPI>(acc[mt][nt][2], acc[mt][nt][3], g0 + 8, c0, z, bias, aux);
        }
    }
}

// ---------------- unified fp32 -> fp16 conversion (one launch, high ILP) -------
// Each block converts 4096 floats (256 thr x 16). All segments divide evenly.
#define CB_TOK ((B_*SQ*TK)/4096)    // 6144
#define CB_PS  ((B_*NS*DM)/4096)    // 256
#define CB_WP  ((TK*DM)/4096)       // 192
#define CB_WG  ((2*DM*DM)/4096)     // 512 per gate weight
__global__ __launch_bounds__(256) void k_convert(const float* __restrict__ toks,
                                                 const float* __restrict__ prev,
                                                 const float* __restrict__ Wp,
                                                 const float* __restrict__ Wu,
                                                 const float* __restrict__ Wr,
                                                 const float* __restrict__ Wn,
                                                 __half* __restrict__ tok_h,
                                                 __half* __restrict__ ps_h,
                                                 __half* __restrict__ Wp_h,
                                                 __half* __restrict__ Wg_h) {
    int b = blockIdx.x;
    const float* src; __half* dst; int i;
    if (b < CB_TOK) { src = toks; dst = tok_h; i = b; }
    else if ((b -= CB_TOK) < CB_PS) { src = prev; dst = ps_h; i = b; }
    else if ((b -= CB_PS) < CB_WP)  { src = Wp;   dst = Wp_h; i = b; }
    else if ((b -= CB_WP) < CB_WG)  { src = Wu;   dst = Wg_h; i = b; }
    else if ((b -= CB_WG) < CB_WG)  { src = Wr;   dst = Wg_h + (size_t)2*DM*DM; i = b; }
    else { b -= CB_WG; src = Wn; dst = Wg_h + (size_t)4*DM*DM; i = b; }
    size_t e = (size_t)i * 4096 + (size_t)threadIdx.x * 16;
    float4 v0 = *reinterpret_cast<const float4*>(src + e);
    float4 v1 = *reinterpret_cast<const float4*>(src + e + 4);
    float4 v2 = *reinterpret_cast<const float4*>(src + e + 8);
    float4 v3 = *reinterpret_cast<const float4*>(src + e + 12);
    __half2 h[8];
    h[0] = __half2(__float2half_rn(v0.x), __float2half_rn(v0.y));
    h[1] = __half2(__float2half_rn(v0.z), __float2half_rn(v0.w));
    h[2] = __half2(__float2half_rn(v1.x), __float2half_rn(v1.y));
    h[3] = __half2(__float2half_rn(v1.z), __float2half_rn(v1.w));
    h[4] = __half2(__float2half_rn(v2.x), __float2half_rn(v2.y));
    h[5] = __half2(__float2half_rn(v2.z), __float2half_rn(v2.w));
    h[6] = __half2(__float2half_rn(v3.x), __float2half_rn(v3.y));
    h[7] = __half2(__float2half_rn(v3.z), __float2half_rn(v3.w));
    *reinterpret_cast<uint4*>(dst + e)     = *reinterpret_cast<uint4*>(&h[0]);
    *reinterpret_cast<uint4*>(dst + e + 8) = *reinterpret_cast<uint4*>(&h[4]);
}

// ---------------- softmax over S (2048), in place on fp16 ----------------------
__global__ __launch_bounds__(256) void k_softmax() {
    const size_t row = blockIdx.x;
    __half* x = g_attn_h + row * SQ;
    const int tid = threadIdx.x;
    __shared__ float red[8], red2[8];

    uint4 raw = reinterpret_cast<uint4*>(x)[tid];       // 8 halfs
    __half2* hp = reinterpret_cast<__half2*>(&raw);
    float v[8];
#pragma unroll
    for (int j = 0; j < 4; ++j) {
        float2 f = __half22float2(hp[j]);
        v[2*j] = f.x; v[2*j+1] = f.y;
    }
    float m = v[0];
#pragma unroll
    for (int j = 1; j < 8; ++j) m = fmaxf(m, v[j]);
    m = warpMax(m);
    if ((tid & 31) == 0) red[tid >> 5] = m;
    __syncthreads();
    m = red[0];
#pragma unroll
    for (int i = 1; i < 8; ++i) m = fmaxf(m, red[i]);

    float s = 0.f;
#pragma unroll
    for (int j = 0; j < 8; ++j) { v[j] = expf(v[j] - m); s += v[j]; }
    s = warpSum(s);
    if ((tid & 31) == 0) red2[tid >> 5] = s;
    __syncthreads();
    s = 0.f;
#pragma unroll
    for (int i = 0; i < 8; ++i) s += red2[i];
    const float inv = 1.0f / s;

#pragma unroll
    for (int j = 0; j < 4; ++j)
        hp[j] = __half2(__float2half_rn(v[2*j] * inv), __float2half_rn(v[2*j+1] * inv));
    reinterpret_cast<uint4*>(x)[tid] = raw;
}

// ---------------- two LayerNorms -> cat / cat2 (fp16) --------------------------
__global__ __launch_bounds__(256) void k_ln_cat(const float* __restrict__ PS,
                                                const float* __restrict__ gs,
                                                const float* __restrict__ bs,
                                                const float* __restrict__ gi,
                                                const float* __restrict__ bi) {
    const int rowId = blockIdx.x;
    const bool isInput = rowId >= B_ * NS;
    const int r = isInput ? rowId - B_ * NS : rowId;
    const float* x = isInput ? (g_routed + (size_t)r * DM) : (PS + (size_t)r * DM);
    const float* gamma = isInput ? gi : gs;
    const float* beta  = isInput ? bi : bs;
    const int tid = threadIdx.x;
    __shared__ float s1[8], s2[8];

    float4 v = reinterpret_cast<const float4*>(x)[tid];
    float sum = v.x + v.y + v.z + v.w;
    float sq  = v.x*v.x + v.y*v.y + v.z*v.z + v.w*v.w;
    sum = warpSum(sum); sq = warpSum(sq);
    if ((tid & 31) == 0) { s1[tid >> 5] = sum; s2[tid >> 5] = sq; }
    __syncthreads();
    sum = 0.f; sq = 0.f;
#pragma unroll
    for (int i = 0; i < 8; ++i) { sum += s1[i]; sq += s2[i]; }
    const float mean = sum * (1.0f / DM);
    const float var  = sq * (1.0f / DM) - mean * mean;
    const float inv  = rsqrtf(var + 1e-5f);

    float4 gv = reinterpret_cast<const float4*>(gamma)[tid];
    float4 bv = reinterpret_cast<const float4*>(beta)[tid];
    __half2 h01 = __half2(__float2half_rn((v.x - mean) * inv * gv.x + bv.x),
                          __float2half_rn((v.y - mean) * inv * gv.y + bv.y));
    __half2 h23 = __half2(__float2half_rn((v.z - mean) * inv * gv.z + bv.z),
                          __float2half_rn((v.w - mean) * inv * gv.w + bv.w));

    const size_t off = (size_t)r * (2 * DM) + (isInput ? DM : 0) + (size_t)tid * 4;
    *reinterpret_cast<__half2*>(&g_cat_h[off])     = h01;
    *reinterpret_cast<__half2*>(&g_cat_h[off + 2]) = h23;
    if (isInput) {
        *reinterpret_cast<__half2*>(&g_cat2_h[off])     = h01;
        *reinterpret_cast<__half2*>(&g_cat2_h[off + 2]) = h23;
    }
}

// ---------------- output LayerNorm ---------------------------------------------
__global__ __launch_bounds__(256) void k_ln_out(const float* __restrict__ go,
                                                const float* __restrict__ bo,
                                                float* __restrict__ out) {
    const int r = blockIdx.x;
    const float* x = g_new + (size_t)r * DM;
    const int tid = threadIdx.x;
    __shared__ float s1[8], s2[8];

    float4 v = reinterpret_cast<const float4*>(x)[tid];
    float sum = v.x + v.y + v.z + v.w;
    float sq  = v.x*v.x + v.y*v.y + v.z*v.z + v.w*v.w;
    sum = warpSum(sum); sq = warpSum(sq);
    if ((tid & 31) == 0) { s1[tid >> 5] = sum; s2[tid >> 5] = sq; }
    __syncthreads();
    sum = 0.f; sq = 0.f;
#pragma unroll
    for (int i = 0; i < 8; ++i) { sum += s1[i]; sq += s2[i]; }
    const float mean = sum * (1.0f / DM);
    const float var  = sq * (1.0f / DM) - mean * mean;
    const float inv  = rsqrtf(var + 1e-5f);

    float4 gv = reinterpret_cast<const float4*>(go)[tid];
    float4 bv = reinterpret_cast<const float4*>(bo)[tid];
    float4 y;
    y.x = (v.x - mean) * inv * gv.x + bv.x;
    y.y = (v.y - mean) * inv * gv.y + bv.y;
    y.z = (v.z - mean) * inv * gv.z + bv.z;
    y.w = (v.w - mean) * inv * gv.w + bv.w;
    reinterpret_cast<float4*>(out + (size_t)r * DM)[tid] = y;
}

// ---------------- launch ---------------------------------------------------------
extern "C" void kernel_launch(void* const* d_in, const int* in_sizes, int n_in,
                              void* d_out, int out_size) {
    (void)in_sizes; (void)n_in; (void)out_size;
    const float* prev = (const float*)d_in[0];
    const float* toks = (const float*)d_in[1];
    const float* Wp   = (const float*)d_in[2];
    const float* bp   = (const float*)d_in[3];
    const float* gs   = (const float*)d_in[4];
    const float* bs   = (const float*)d_in[5];
    const float* gi   = (const float*)d_in[6];
    const float* bi   = (const float*)d_in[7];
    const float* go   = (const float*)d_in[8];
    const float* bo   = (const float*)d_in[9];
    const float* Wu   = (const float*)d_in[10];
    const float* bu   = (const float*)d_in[11];
    const float* Wr   = (const float*)d_in[12];
    const float* br   = (const float*)d_in[13];
    const float* Wn   = (const float*)d_in[14];
    const float* bn   = (const float*)d_in[15];
    float* out = (float*)d_out;

    __half *tok_h, *ps_h, *Wp_h, *Wg_h, *th, *ah, *ch, *c2h;
    cudaGetSymbolAddress((void**)&tok_h, g_tokens_h);
    cudaGetSymbolAddress((void**)&ps_h,  g_ps_h);
    cudaGetSymbolAddress((void**)&Wp_h,  g_Wp_h);
    cudaGetSymbolAddress((void**)&Wg_h,  g_Wg_h);
    cudaGetSymbolAddress((void**)&th,  g_tok_h);
    cudaGetSymbolAddress((void**)&ah,  g_attn_h);
    cudaGetSymbolAddress((void**)&ch,  g_cat_h);
    cudaGetSymbolAddress((void**)&c2h, g_cat2_h);

    // dynamic smem sizes (bytes), 4-stage
    constexpr int SM_BIG     = (4*128*40 + 4*32*136) * 2;  // 75776 (128x128, BT=false)
    constexpr int SM_S64     = (4*64*40  + 4*64*40) * 2;   // 40960 (64x64, BT=true)
    constexpr int SM_N64     = (4*64*40  + 4*32*72) * 2;   // 38912 (64x64, BT=false)

    cudaFuncSetAttribute((const void*)gemm1<128,128,64,32,false,0,  TK,  TK,  DM>, cudaFuncAttributeMaxDynamicSharedMemorySize, SM_BIG);
    cudaFuncSetAttribute((const void*)gemm1<64,64,32,16,true,1,     DM,  DM,  DM>, cudaFuncAttributeMaxDynamicSharedMemorySize, SM_S64);
    cudaFuncSetAttribute((const void*)gemm1<64,64,32,16,false,2,    SQ,  SQ,  DM>, cudaFuncAttributeMaxDynamicSharedMemorySize, SM_N64);
    cudaFuncSetAttribute((const void*)gemm1<64,64,32,16,false,34,  2*DM,2*DM, DM>, cudaFuncAttributeMaxDynamicSharedMemorySize, SM_N64);
    cudaFuncSetAttribute((const void*)gemm1<64,64,32,16,false,5,   2*DM,2*DM, DM>, cudaFuncAttributeMaxDynamicSharedMemorySize, SM_N64);

    const long long WSTRIDE = (long long)2 * DM * DM;

    // 1) all fp32->fp16 conversions in ONE launch (16 floats/thread)
    k_convert<<<CB_TOK + CB_PS + CB_WP + 3*CB_WG, 256>>>(
        toks, prev, Wp, Wu, Wr, Wn, tok_h, ps_h, Wp_h, Wg_h);

    // 2) proj: tok = tokens @ W_proj + b   (M=32768,N=1024,K=768) NN
    gemm1<128,128,64,32,false,0, TK, TK, DM><<<dim3(DM/128, (B_*SQ)/128, 1), 256, SM_BIG>>>(
        tok_h, Wp_h, 0, 0, 0, bp, nullptr, nullptr);

    // 3) scores: ps @ tok^T (per batch, M=64,N=2048,K=1024) TN -> fp16 (512 CTAs)
    gemm1<64,64,32,16,true,1, DM, DM, DM><<<dim3(SQ/64, 1, B_), 256, SM_S64>>>(
        ps_h, th, (long long)NS*DM, (long long)SQ*DM, NS, nullptr, nullptr, nullptr);

    // 4) softmax in place on fp16 scores -> attn
    k_softmax<<<B_*NS, 256>>>();

    // 5) routed: attn @ tok (per batch, M=64,N=1024,K=2048) NN (256 CTAs)
    gemm1<64,64,32,16,false,2, SQ, SQ, DM><<<dim3(DM/64, 1, B_), 256, SM_N64>>>(
        ah, th, (long long)NS*SQ, (long long)SQ*DM, NS, nullptr, nullptr, nullptr);

    // 6) LN(prev), LN(routed) -> cat / cat2
    k_ln_cat<<<2*B_*NS, 256>>>(prev, gs, bs, gi, bi);

    // 7) gates u (z=0) and r (z=1) in ONE launch (512 CTAs)
    gemm1<64,64,32,16,false,34, 2*DM, 2*DM, DM><<<dim3(DM/64, (B_*NS)/64, 2), 256, SM_N64>>>(
        ch, Wg_h, 0, WSTRIDE, 0, bu, br, nullptr);

    // 8) cand + gated combine (256 CTAs)
    gemm1<64,64,32,16,false,5, 2*DM, 2*DM, DM><<<dim3(DM/64, (B_*NS)/64, 1), 256, SM_N64>>>(
        c2h, Wg_h + 2*WSTRIDE, 0, 0, 0, bn, nullptr, prev);

    // 9) output LN
    k_ln_out<<<B_*NS, 256>>>(go, bo, out);
}

// round 12
// speedup vs baseline: 1.8379x; 1.8379x over previous
#include <cuda_runtime.h>
#include <cuda_fp16.h>
#include <stdint.h>

// Shapes (fixed)
#define B_  16
#define NS  64
#define SQ  2048
#define DM  1024
#define TK  768

// ---------------- scratch (device globals) ----------------------------------
__device__ __align__(16) __half g_tokens_h[(size_t)B_*SQ*TK];            // tokens fp16
__device__ __align__(16) __half g_Wp_h[TK*DM];                           // W_proj fp16
__device__ __align__(16) __half g_Wg_h[3*(size_t)2*DM*DM];               // [Wu | Wr | Wn]
__device__ __align__(16) __half g_ps_h[B_*NS*DM];                        // prev_states fp16
__device__ __align__(16) __half g_psW_h[B_*NS*TK];                       // ps @ Wp^T
__device__ __align__(16) __half g_attn_h[B_*NS*SQ];                      // scores -> attn (fp16)
__device__ __align__(16) __half g_atok_h[B_*NS*TK];                      // attn @ tokens
__device__ __align__(16) float g_routed[B_*NS*DM];
__device__ __align__(16) __half g_cat_h[B_*NS*2*DM];                     // A of gates
__device__ __align__(16) __half g_cat2_h[B_*NS*2*DM];                    // A of cand
__device__ __align__(16) float g_u[B_*NS*DM];
__device__ __align__(16) float g_new[B_*NS*DM];

// ---------------- helpers ----------------------------------------------------
__device__ __forceinline__ unsigned s32(const void* p) {
    return (unsigned)__cvta_generic_to_shared(p);
}
__device__ __forceinline__ void cp16(unsigned dst, const void* src) {
    asm volatile("cp.async.cg.shared.global [%0], [%1], 16;\n" :: "r"(dst), "l"(src) : "memory");
}
__device__ __forceinline__ void cp_commit() { asm volatile("cp.async.commit_group;\n" ::); }
__device__ __forceinline__ void ldm_x4(uint32_t* r, unsigned a) {
    asm volatile("ldmatrix.sync.aligned.m8n8.x4.shared.b16 {%0,%1,%2,%3}, [%4];\n"
                 : "=r"(r[0]), "=r"(r[1]), "=r"(r[2]), "=r"(r[3]) : "r"(a));
}
__device__ __forceinline__ void ldm_x4_t(uint32_t* r, unsigned a) {
    asm volatile("ldmatrix.sync.aligned.m8n8.x4.trans.shared.b16 {%0,%1,%2,%3}, [%4];\n"
                 : "=r"(r[0]), "=r"(r[1]), "=r"(r[2]), "=r"(r[3]) : "r"(a));
}
__device__ __forceinline__ void mma16816(float* c, const uint32_t* a, const uint32_t* b) {
    asm volatile("mma.sync.aligned.m16n8k16.row.col.f32.f16.f16.f32 "
                 "{%0,%1,%2,%3}, {%4,%5,%6,%7}, {%8,%9}, {%0,%1,%2,%3};\n"
                 : "+f"(c[0]), "+f"(c[1]), "+f"(c[2]), "+f"(c[3])
                 : "r"(a[0]), "r"(a[1]), "r"(a[2]), "r"(a[3]), "r"(b[0]), "r"(b[1]));
}
__device__ __forceinline__ float warpSum(float v) {
#pragma unroll
    for (int o = 16; o; o >>= 1) v += __shfl_xor_sync(0xffffffffu, v, o);
    return v;
}
__device__ __forceinline__ float warpMax(float v) {
#pragma unroll
    for (int o = 16; o; o >>= 1) v = fmaxf(v, __shfl_xor_sync(0xffffffffu, v, o));
    return v;
}

// ---------------- fused vectorized epilogues ----------------------------------
// EPI: 1=scores*scale->fp16  2=routed(+bias) fp32  34=u/r gates  5=cand
//      6=psW fp16            7=attnTok fp16
template<int EPI>
__device__ __forceinline__ void epi2(float a0, float a1, size_t gr, int c, int z,
                                     const float* __restrict__ bias,
                                     const float* __restrict__ aux) {
    if constexpr (EPI == 1) {
        *reinterpret_cast<__half2*>(&g_attn_h[gr * SQ + c]) =
            __half2(__float2half_rn(a0 * 0.03125f), __float2half_rn(a1 * 0.03125f));
    } else if constexpr (EPI == 2) {
        *reinterpret_cast<float2*>(&g_routed[gr * DM + c]) =
            make_float2(a0 + bias[c], a1 + bias[c + 1]);
    } else if constexpr (EPI == 34) {
        float s0 = 1.0f / (1.0f + expf(-(a0 + bias[c])));
        float s1 = 1.0f / (1.0f + expf(-(a1 + bias[c + 1])));
        if (z == 0) {
            *reinterpret_cast<float2*>(&g_u[gr * DM + c]) = make_float2(s0, s1);
        } else {
            size_t i = gr * (2 * DM) + c;
            __half2 ps = *reinterpret_cast<__half2*>(&g_cat_h[i]);
            *reinterpret_cast<__half2*>(&g_cat2_h[i]) =
                __half2(__float2half_rn(s0 * __half2float(ps.x)),
                        __float2half_rn(s1 * __half2float(ps.y)));
        }
    } else if constexpr (EPI == 5) {
        size_t i = gr * DM + c;
        float2 u = *reinterpret_cast<const float2*>(&g_u[i]);
        float2 pv = *reinterpret_cast<const float2*>(&aux[i]);
        float t0 = tanhf(a0 + bias[c]), t1 = tanhf(a1 + bias[c + 1]);
        *reinterpret_cast<float2*>(&g_new[i]) =
            make_float2((1.0f - u.x) * pv.x + u.x * t0,
                        (1.0f - u.y) * pv.y + u.y * t1);
    } else if constexpr (EPI == 6) {
        *reinterpret_cast<__half2*>(&g_psW_h[gr * TK + c]) =
            __half2(__float2half_rn(a0), __float2half_rn(a1));
    } else {
        *reinterpret_cast<__half2*>(&g_atok_h[gr * TK + c]) =
            __half2(__float2half_rn(a0), __float2half_rn(a1));
    }
}

// ---------------- single-pass fp16 GEMM, 4-stage pipeline, unroll-4 -----------
template<int BM, int BN, int WM, int WN, bool BT, int EPI, int K, int LDA, int LDB>
__global__ __launch_bounds__(256, 2)
void gemm1(const __half* __restrict__ A, const __half* __restrict__ B,
           long long zA, long long zB, int rowz,
           const float* __restrict__ bias0, const float* __restrict__ bias1,
           const float* __restrict__ aux)
{
    constexpr int BK  = 32;
    constexpr int NST = 4;
    constexpr int WMs = BM / WM;
    constexpr int MT  = WM / 16, NT = WN / 8;
    constexpr int AST = BK + 8;
    constexpr int BST = BK + 8;
    constexpr int BNP = BN + 8;
    constexpr int nk  = K / BK;
    static_assert(nk % 4 == 0 && nk >= 4, "nk must be multiple of 4");

    extern __shared__ __align__(16) __half sm[];
    __half* As = sm;
    __half* Bs = sm + NST * BM * AST;

    const int tid = threadIdx.x, lane = tid & 31, wid = tid >> 5;
    const int wm = wid % WMs, wn = wid / WMs;
    const int brow = blockIdx.y * BM, bcol = blockIdx.x * BN;
    const int z = blockIdx.z;

    const __half* Ap = A + (size_t)z * zA + (size_t)brow * LDA;
    const __half* Bp = B + (size_t)z * zB;

    float acc[MT][NT][4];
#pragma unroll
    for (int i = 0; i < MT; ++i)
#pragma unroll
        for (int j = 0; j < NT; ++j)
#pragma unroll
            for (int e = 0; e < 4; ++e) acc[i][j][e] = 0.f;

    auto aOfs = [](int buf, int r, int c) -> int { return (buf * BM + r) * AST + c; };
    auto bOfs = [](int buf, int r, int c) -> int {
        return BT ? ((buf * BN + r) * BST + c) : ((buf * BK + r) * BNP + c);
    };

    constexpr int A_IT = BM * 4 / 256;
    constexpr int B_IT = BT ? (BN * 4 / 256) : (BK * BN / 8 / 256);

    auto loadSlab = [&](int buf, int k0) {
#pragma unroll
        for (int it = 0; it < A_IT; ++it) {
            int i = tid + it * 256;
            int r = i >> 2, c = (i & 3) * 8;
            cp16(s32(&As[aOfs(buf, r, c)]), Ap + (size_t)r * LDA + k0 + c);
        }
        if (BT) {
#pragma unroll
            for (int it = 0; it < B_IT; ++it) {
                int i = tid + it * 256;
                int n = i >> 2, c = (i & 3) * 8;
                cp16(s32(&Bs[bOfs(buf, n, c)]), Bp + (size_t)(bcol + n) * LDB + k0 + c);
            }
        } else {
#pragma unroll
            for (int it = 0; it < B_IT; ++it) {
                int i = tid + it * 256;
                int k = i / (BN / 8); int n8 = (i % (BN / 8)) * 8;
                cp16(s32(&Bs[bOfs(buf, k, n8)]), Bp + (size_t)(k0 + k) * LDB + bcol + n8);
            }
        }
        cp_commit();
    };

    loadSlab(0, 0);
    loadSlab(1, BK);
    loadSlab(2, 2 * BK);

#pragma unroll 4
    for (int ks = 0; ks < nk; ++ks) {
        const int buf = ks & 3;
        asm volatile("cp.async.wait_group 2;\n" ::);
        __syncthreads();
        if (ks + 3 < nk) loadSlab((ks + 3) & 3, (ks + 3) * BK);
        else cp_commit();

#pragma unroll
        for (int kk2 = 0; kk2 < 2; ++kk2) {
            uint32_t af[MT][4];
#pragma unroll
            for (int mt = 0; mt < MT; ++mt) {
                int row = wm * WM + mt * 16 + (lane & 15);
                int col = kk2 * 16 + (lane >> 4) * 8;
                ldm_x4(af[mt], s32(&As[aOfs(buf, row, col)]));
            }
            uint32_t bf[NT][2];
#pragma unroll
            for (int p = 0; p < NT / 2; ++p) {
                int nbase = wn * WN + p * 16;
                uint32_t t[4];
                if (BT) {
                    int r = nbase + (lane & 7) + ((lane >> 4) << 3);
                    int c = kk2 * 16 + ((lane >> 3) & 1) * 8;
                    ldm_x4(t, s32(&Bs[bOfs(buf, r, c)]));
                } else {
                    int k = kk2 * 16 + (lane & 15);
                    int nc = nbase + ((lane >> 4) << 3);
                    ldm_x4_t(t, s32(&Bs[bOfs(buf, k, nc)]));
                }
                bf[2*p][0]=t[0]; bf[2*p][1]=t[1]; bf[2*p+1][0]=t[2]; bf[2*p+1][1]=t[3];
            }
#pragma unroll
            for (int mt = 0; mt < MT; ++mt)
#pragma unroll
                for (int nt = 0; nt < NT; ++nt)
                    mma16816(acc[mt][nt], af[mt], bf[nt]);
        }
    }

    const float* bias = (z != 0 && bias1) ? bias1 : bias0;
#pragma unroll
    for (int mt = 0; mt < MT; ++mt) {
        int r0 = brow + wm * WM + mt * 16 + (lane >> 2);
#pragma unroll
        for (int nt = 0; nt < NT; ++nt) {
            int c0 = bcol + wn * WN + nt * 8 + ((lane & 3) << 1);
            size_t g0 = (size_t)z * rowz + r0;
            epi2<EPI>(acc[mt][nt][0], acc[mt][nt][1], g0,     c0, z, bias, aux);
            epi2<EPI>(acc[mt][nt][2], acc[mt][nt][3], g0 + 8, c0, z, bias, aux);
        }
    }
}

// ---------------- unified fp32 -> fp16 conversion (one launch, high ILP) -------
// Each block converts 4096 floats (256 thr x 16). All segments divide evenly.
#define CB_TOK ((B_*SQ*TK)/4096)    // 6144
#define CB_PS  ((B_*NS*DM)/4096)    // 256
#define CB_WP  ((TK*DM)/4096)       // 192
#define CB_WG  ((2*DM*DM)/4096)     // 512 per gate weight
__global__ __launch_bounds__(256) void k_convert(const float* __restrict__ toks,
                                                 const float* __restrict__ prev,
                                                 const float* __restrict__ Wp,
                                                 const float* __restrict__ Wu,
                                                 const float* __restrict__ Wr,
                                                 const float* __restrict__ Wn,
                                                 __half* __restrict__ tok_h,
                                                 __half* __restrict__ ps_h,
                                                 __half* __restrict__ Wp_h,
                                                 __half* __restrict__ Wg_h) {
    int b = blockIdx.x;
    const float* src; __half* dst; int i;
    if (b < CB_TOK) { src = toks; dst = tok_h; i = b; }
    else if ((b -= CB_TOK) < CB_PS) { src = prev; dst = ps_h; i = b; }
    else if ((b -= CB_PS) < CB_WP)  { src = Wp;   dst = Wp_h; i = b; }
    else if ((b -= CB_WP) < CB_WG)  { src = Wu;   dst = Wg_h; i = b; }
    else if ((b -= CB_WG) < CB_WG)  { src = Wr;   dst = Wg_h + (size_t)2*DM*DM; i = b; }
    else { b -= CB_WG; src = Wn; dst = Wg_h + (size_t)4*DM*DM; i = b; }
    size_t e = (size_t)i * 4096 + (size_t)threadIdx.x * 16;
    float4 v0 = *reinterpret_cast<const float4*>(src + e);
    float4 v1 = *reinterpret_cast<const float4*>(src + e + 4);
    float4 v2 = *reinterpret_cast<const float4*>(src + e + 8);
    float4 v3 = *reinterpret_cast<const float4*>(src + e + 12);
    __half2 h[8];
    h[0] = __half2(__float2half_rn(v0.x), __float2half_rn(v0.y));
    h[1] = __half2(__float2half_rn(v0.z), __float2half_rn(v0.w));
    h[2] = __half2(__float2half_rn(v1.x), __float2half_rn(v1.y));
    h[3] = __half2(__float2half_rn(v1.z), __float2half_rn(v1.w));
    h[4] = __half2(__float2half_rn(v2.x), __float2half_rn(v2.y));
    h[5] = __half2(__float2half_rn(v2.z), __float2half_rn(v2.w));
    h[6] = __half2(__float2half_rn(v3.x), __float2half_rn(v3.y));
    h[7] = __half2(__float2half_rn(v3.z), __float2half_rn(v3.w));
    *reinterpret_cast<uint4*>(dst + e)     = *reinterpret_cast<uint4*>(&h[0]);
    *reinterpret_cast<uint4*>(dst + e + 8) = *reinterpret_cast<uint4*>(&h[4]);
}

// ---------------- softmax over S (2048), in place on fp16 ----------------------
__global__ __launch_bounds__(256) void k_softmax() {
    const size_t row = blockIdx.x;
    __half* x = g_attn_h + row * SQ;
    const int tid = threadIdx.x;
    __shared__ float red[8], red2[8];

    uint4 raw = reinterpret_cast<uint4*>(x)[tid];       // 8 halfs
    __half2* hp = reinterpret_cast<__half2*>(&raw);
    float v[8];
#pragma unroll
    for (int j = 0; j < 4; ++j) {
        float2 f = __half22float2(hp[j]);
        v[2*j] = f.x; v[2*j+1] = f.y;
    }
    float m = v[0];
#pragma unroll
    for (int j = 1; j < 8; ++j) m = fmaxf(m, v[j]);
    m = warpMax(m);
    if ((tid & 31) == 0) red[tid >> 5] = m;
    __syncthreads();
    m = red[0];
#pragma unroll
    for (int i = 1; i < 8; ++i) m = fmaxf(m, red[i]);

    float s = 0.f;
#pragma unroll
    for (int j = 0; j < 8; ++j) { v[j] = expf(v[j] - m); s += v[j]; }
    s = warpSum(s);
    if ((tid & 31) == 0) red2[tid >> 5] = s;
    __syncthreads();
    s = 0.f;
#pragma unroll
    for (int i = 0; i < 8; ++i) s += red2[i];
    const float inv = 1.0f / s;

#pragma unroll
    for (int j = 0; j < 4; ++j)
        hp[j] = __half2(__float2half_rn(v[2*j] * inv), __float2half_rn(v[2*j+1] * inv));
    reinterpret_cast<uint4*>(x)[tid] = raw;
}

// ---------------- two LayerNorms -> cat / cat2 (fp16) --------------------------
__global__ __launch_bounds__(256) void k_ln_cat(const float* __restrict__ PS,
                                                const float* __restrict__ gs,
                                                const float* __restrict__ bs,
                                                const float* __restrict__ gi,
                                                const float* __restrict__ bi) {
    const int rowId = blockIdx.x;
    const bool isInput = rowId >= B_ * NS;
    const int r = isInput ? rowId - B_ * NS : rowId;
    const float* x = isInput ? (g_routed + (size_t)r * DM) : (PS + (size_t)r * DM);
    const float* gamma = isInput ? gi : gs;
    const float* beta  = isInput ? bi : bs;
    const int tid = threadIdx.x;
    __shared__ float s1[8], s2[8];

    float4 v = reinterpret_cast<const float4*>(x)[tid];
    float sum = v.x + v.y + v.z + v.w;
    float sq  = v.x*v.x + v.y*v.y + v.z*v.z + v.w*v.w;
    sum = warpSum(sum); sq = warpSum(sq);
    if ((tid & 31) == 0) { s1[tid >> 5] = sum; s2[tid >> 5] = sq; }
    __syncthreads();
    sum = 0.f; sq = 0.f;
#pragma unroll
    for (int i = 0; i < 8; ++i) { sum += s1[i]; sq += s2[i]; }
    const float mean = sum * (1.0f / DM);
    const float var  = sq * (1.0f / DM) - mean * mean;
    const float inv  = rsqrtf(var + 1e-5f);

    float4 gv = reinterpret_cast<const float4*>(gamma)[tid];
    float4 bv = reinterpret_cast<const float4*>(beta)[tid];
    __half2 h01 = __half2(__float2half_rn((v.x - mean) * inv * gv.x + bv.x),
                          __float2half_rn((v.y - mean) * inv * gv.y + bv.y));
    __half2 h23 = __half2(__float2half_rn((v.z - mean) * inv * gv.z + bv.z),
                          __float2half_rn((v.w - mean) * inv * gv.w + bv.w));

    const size_t off = (size_t)r * (2 * DM) + (isInput ? DM : 0) + (size_t)tid * 4;
    *reinterpret_cast<__half2*>(&g_cat_h[off])     = h01;
    *reinterpret_cast<__half2*>(&g_cat_h[off + 2]) = h23;
    if (isInput) {
        *reinterpret_cast<__half2*>(&g_cat2_h[off])     = h01;
        *reinterpret_cast<__half2*>(&g_cat2_h[off + 2]) = h23;
    }
}

// ---------------- output LayerNorm ---------------------------------------------
__global__ __launch_bounds__(256) void k_ln_out(const float* __restrict__ go,
                                                const float* __restrict__ bo,
                                                float* __restrict__ out) {
    const int r = blockIdx.x;
    const float* x = g_new + (size_t)r * DM;
    const int tid = threadIdx.x;
    __shared__ float s1[8], s2[8];

    float4 v = reinterpret_cast<const float4*>(x)[tid];
    float sum = v.x + v.y + v.z + v.w;
    float sq  = v.x*v.x + v.y*v.y + v.z*v.z + v.w*v.w;
    sum = warpSum(sum); sq = warpSum(sq);
    if ((tid & 31) == 0) { s1[tid >> 5] = sum; s2[tid >> 5] = sq; }
    __syncthreads();
    sum = 0.f; sq = 0.f;
#pragma unroll
    for (int i = 0; i < 8; ++i) { sum += s1[i]; sq += s2[i]; }
    const float mean = sum * (1.0f / DM);
    const float var  = sq * (1.0f / DM) - mean * mean;
    const float inv  = rsqrtf(var + 1e-5f);

    float4 gv = reinterpret_cast<const float4*>(go)[tid];
    float4 bv = reinterpret_cast<const float4*>(bo)[tid];
    float4 y;
    y.x = (v.x - mean) * inv * gv.x + bv.x;
    y.y = (v.y - mean) * inv * gv.y + bv.y;
    y.z = (v.z - mean) * inv * gv.z + bv.z;
    y.w = (v.w - mean) * inv * gv.w + bv.w;
    reinterpret_cast<float4*>(out + (size_t)r * DM)[tid] = y;
}

// ---------------- launch ---------------------------------------------------------
extern "C" void kernel_launch(void* const* d_in, const int* in_sizes, int n_in,
                              void* d_out, int out_size) {
    (void)in_sizes; (void)n_in; (void)out_size;
    const float* prev = (const float*)d_in[0];
    const float* toks = (const float*)d_in[1];
    const float* Wp   = (const float*)d_in[2];
    const float* bp   = (const float*)d_in[3];
    const float* gs   = (const float*)d_in[4];
    const float* bs   = (const float*)d_in[5];
    const float* gi   = (const float*)d_in[6];
    const float* bi   = (const float*)d_in[7];
    const float* go   = (const float*)d_in[8];
    const float* bo   = (const float*)d_in[9];
    const float* Wu   = (const float*)d_in[10];
    const float* bu   = (const float*)d_in[11];
    const float* Wr   = (const float*)d_in[12];
    const float* br   = (const float*)d_in[13];
    const float* Wn   = (const float*)d_in[14];
    const float* bn   = (const float*)d_in[15];
    float* out = (float*)d_out;

    __half *tok_h, *ps_h, *Wp_h, *Wg_h, *psW_h, *ah, *atok_h, *ch, *c2h;
    cudaGetSymbolAddress((void**)&tok_h, g_tokens_h);
    cudaGetSymbolAddress((void**)&ps_h,  g_ps_h);
    cudaGetSymbolAddress((void**)&Wp_h,  g_Wp_h);
    cudaGetSymbolAddress((void**)&Wg_h,  g_Wg_h);
    cudaGetSymbolAddress((void**)&psW_h, g_psW_h);
    cudaGetSymbolAddress((void**)&ah,    g_attn_h);
    cudaGetSymbolAddress((void**)&atok_h,g_atok_h);
    cudaGetSymbolAddress((void**)&ch,    g_cat_h);
    cudaGetSymbolAddress((void**)&c2h,   g_cat2_h);

    // dynamic smem sizes (bytes), 4-stage
    constexpr int SM_BIG    = (4*128*40 + 4*32*136) * 2;   // 75776 (128x128, BT=false)
    constexpr int SM_TN     = (4*64*40  + 4*128*40) * 2;   // 61440 (64x128, BT=true)
    constexpr int SM_NN     = (4*64*40  + 4*32*136) * 2;   // 55296 (64x128, BT=false)

    cudaFuncSetAttribute((const void*)gemm1<64,128,32,32,true,6,    DM,  DM,  DM>, cudaFuncAttributeMaxDynamicSharedMemorySize, SM_TN);
    cudaFuncSetAttribute((const void*)gemm1<64,128,32,32,true,1,    TK,  TK,  TK>, cudaFuncAttributeMaxDynamicSharedMemorySize, SM_TN);
    cudaFuncSetAttribute((const void*)gemm1<64,128,32,32,false,7,   SQ,  SQ,  TK>, cudaFuncAttributeMaxDynamicSharedMemorySize, SM_NN);
    cudaFuncSetAttribute((const void*)gemm1<64,128,32,32,false,2,   TK,  TK,  DM>, cudaFuncAttributeMaxDynamicSharedMemorySize, SM_NN);
    cudaFuncSetAttribute((const void*)gemm1<128,128,64,32,false,34, 2*DM,2*DM,DM>, cudaFuncAttributeMaxDynamicSharedMemorySize, SM_BIG);
    cudaFuncSetAttribute((const void*)gemm1<64,128,32,32,false,5,   2*DM,2*DM,DM>, cudaFuncAttributeMaxDynamicSharedMemorySize, SM_NN);

    const long long WSTRIDE = (long long)2 * DM * DM;

    // 1) all fp32->fp16 conversions in ONE launch
    k_convert<<<CB_TOK + CB_PS + CB_WP + 3*CB_WG, 256>>>(
        toks, prev, Wp, Wu, Wr, Wn, tok_h, ps_h, Wp_h, Wg_h);

    // 2) psW = ps @ Wp^T  (TN, M=1024, N=768, K=1024) -> fp16   [96 CTAs]
    gemm1<64,128,32,32,true,6, DM, DM, DM><<<dim3(TK/128, (B_*NS)/64, 1), 256, SM_TN>>>(
        ps_h, Wp_h, 0, 0, 0, nullptr, nullptr, nullptr);

    // 3) scores = psW @ tokens^T (TN per batch, M=64, N=2048, K=768) -> fp16 *1/32
    gemm1<64,128,32,32,true,1, TK, TK, TK><<<dim3(SQ/128, 1, B_), 256, SM_TN>>>(
        psW_h, tok_h, (long long)NS*TK, (long long)SQ*TK, NS, nullptr, nullptr, nullptr);

    // 4) softmax in place on fp16 scores -> attn
    k_softmax<<<B_*NS, 256>>>();

    // 5) attnTok = attn @ tokens (NN per batch, M=64, N=768, K=2048) -> fp16
    gemm1<64,128,32,32,false,7, SQ, SQ, TK><<<dim3(TK/128, 1, B_), 256, SM_NN>>>(
        ah, tok_h, (long long)NS*SQ, (long long)SQ*TK, NS, nullptr, nullptr, nullptr);

    // 6) routed = attnTok @ Wp + bp (NN, M=1024, N=1024, K=768) -> fp32
    gemm1<64,128,32,32,false,2, TK, TK, DM><<<dim3(DM/128, (B_*NS)/64, 1), 256, SM_NN>>>(
        atok_h, Wp_h, 0, 0, 0, bp, nullptr, nullptr);

    // 7) LN(prev), LN(routed) -> cat / cat2
    k_ln_cat<<<2*B_*NS, 256>>>(prev, gs, bs, gi, bi);

    // 8) gates u (z=0) and r (z=1) in ONE launch (M=1024,N=1024,K=2048) NN
    gemm1<128,128,64,32,false,34, 2*DM, 2*DM, DM><<<dim3(DM/128, (B_*NS)/128, 2), 256, SM_BIG>>>(
        ch, Wg_h, 0, WSTRIDE, 0, bu, br, nullptr);

    // 9) cand + gated combine (BM=64 -> 128 CTAs)
    gemm1<64,128,32,32,false,5, 2*DM, 2*DM, DM><<<dim3(DM/128, (B_*NS)/64, 1), 256, SM_NN>>>(
        c2h, Wg_h + 2*WSTRIDE, 0, 0, 0, bn, nullptr, prev);

    // 10) output LN
    k_ln_out<<<B_*NS, 256>>>(go, bo, out);
}